// round 15
// baseline (speedup 1.0000x reference)
#include <cuda_runtime.h>
#include <cuda_bf16.h>

// ---------------- problem constants ----------------
constexpr int Bsz  = 8;
constexpr int Lseq = 1024;
constexpr int DM   = 256;   // d_model
constexpr int DI   = 512;   // d_inner
constexpr int DS   = 16;    // d_state
constexpr int DR   = 16;    // dt_rank
constexpr int KD   = 4;     // directions
constexpr int CC   = DR + 2*DS;  // 48
constexpr int NCH  = 32;    // scan chunks
constexpr int LC   = Lseq/NCH;   // 32 steps per chunk
constexpr int ROW4 = (KD*CC)/4;  // 48 float4 per (b,lam) row of g_P

// ---------------- scratch (device globals; no allocation) ----------------
__device__ float g_xssm[Bsz*Lseq*DI];
__device__ float g_z   [Bsz*Lseq*DI];
__device__ float g_xcT [Bsz*Lseq*DI];
__device__ float g_P   [Bsz*Lseq*KD*CC];
__device__ float g_ysum[Bsz*Lseq*DI];
__device__ float g_ydir[KD*Bsz*Lseq*DI];
__device__ float g_hout[Bsz*KD*NCH*DI*DS];
__device__ float g_hin [Bsz*KD*NCH*DI*DS];
__device__ float g_S   [Bsz*KD*NCH*DI];
__device__ float2 g_due1[(size_t)KD*Bsz*Lseq*DI];   // (du, e1) per step
__device__ int    g_chainflag;

__device__ __forceinline__ float siluf(float v){
    return v * (1.0f / (1.0f + __expf(-v)));
}
__device__ __forceinline__ unsigned f2tf(float f){
    unsigned u; asm("cvt.rna.tf32.f32 %0, %1;" : "=r"(u) : "f"(f)); return u;
}
__device__ __forceinline__ void mma_tf32(float (&c)[4], const unsigned (&a)[4], const unsigned (&b)[2]){
    asm volatile(
        "mma.sync.aligned.m16n8k8.row.col.f32.tf32.tf32.f32 "
        "{%0,%1,%2,%3}, {%4,%5,%6,%7}, {%8,%9}, {%0,%1,%2,%3};\n"
        : "+f"(c[0]), "+f"(c[1]), "+f"(c[2]), "+f"(c[3])
        : "r"(a[0]), "r"(a[1]), "r"(a[2]), "r"(a[3]), "r"(b[0]), "r"(b[1]));
}

// -------- packed f32x2 helpers --------
typedef unsigned long long ull;
__device__ __forceinline__ ull pk2(float lo, float hi){
    ull r; asm("mov.b64 %0, {%1,%2};" : "=l"(r) : "f"(lo), "f"(hi)); return r;
}
__device__ __forceinline__ void upk2(ull v, float& lo, float& hi){
    asm("mov.b64 {%0,%1}, %2;" : "=f"(lo), "=f"(hi) : "l"(v));
}
__device__ __forceinline__ ull fma2(ull a, ull b, ull c){
    ull d; asm("fma.rn.f32x2 %0, %1, %2, %3;" : "=l"(d) : "l"(a), "l"(b), "l"(c)); return d;
}
__device__ __forceinline__ ull mul2(ull a, ull b){
    ull d; asm("mul.rn.f32x2 %0, %1, %2;" : "=l"(d) : "l"(a), "l"(b)); return d;
}
__device__ __forceinline__ ull add2(ull a, ull b){
    ull d; asm("add.rn.f32x2 %0, %1, %2;" : "=l"(d) : "l"(a), "l"(b)); return d;
}

// ---------------- tf32 tensor-core GEMM, fragment-permuted smem ----------------
// MODE 0: A=x (Mx256), W=in_proj_w; split -> g_xssm / silu -> g_z   (BM=128, BK=16)
// MODE 1: A=g_ysum (Mx512), W=out_proj_w; write outp (Mx256)        (BM=128, BK=16)
// MODE 2: A=g_xcT (Mx512), W=x_proj_w (192x512); write g_P (Mx192)  (BM=64,  BK=32)
// Smem layout: As[k8][m16-tile][lane*4 + slot], slot = rhi + khi*2 (mma a-frag order)
//              Ws[k8][n8-tile ][lane*2 + khi]                      (mma b-frag order)
template<int KDIM, int MODE, int BM, int BK>
__global__ __launch_bounds__(BM==128?256:128, BM==128?2:4)
void gemm_tc(const float* __restrict__ Ain,
             const float* __restrict__ W,
             float* __restrict__ outp){
    constexpr int BN=64;
    constexpr int K8 = BK/8;
    constexpr int MT = BM/16;
    constexpr int NT = BN/8;
    constexpr int WM = BM/32;
    constexpr int ALD = (BK==16)?8:16;
    constexpr int WLD = (BK==32)?16:((BM==128)?4:8);
    __shared__ alignas(16) unsigned As[2][K8][MT][128];
    __shared__ alignas(16) unsigned Ws[2][K8][NT][64];
    const float* A = (MODE==0) ? Ain : (MODE==1 ? (const float*)g_ysum : (const float*)g_xcT);
    const int m0 = blockIdx.x*BM, n0 = blockIdx.y*BN;
    const int tid = threadIdx.x;
    const int wid = tid>>5, lane = tid&31;
    const int wm = wid % WM, wn = wid / WM;
    const int g = lane>>2, tg = lane&3;

    const int alr = tid>>1, alc = (tid&1)*ALD;
    const int wlr = (BK==32) ? (tid>>1) : ((BM==128)?(tid>>2):(tid>>1));
    const int wlc = (BK==32) ? (tid&1)*16 : ((BM==128)?((tid&3)*4):((tid&1)*8));

    const float* Ap = A + (size_t)(m0+alr)*KDIM + alc;
    const float* Wp = W + (size_t)(n0+wlr)*KDIM + wlc;

    // permuted-store index helpers (thread-constant per j; hoisted by compiler)
    const int a_mt  = alr>>4;
    const int a_g   = (alr&15)&7;
    const int a_rhi = (alr&15)>>3;
    const int w_nt  = wlr>>3;
    const int w_g   = wlr&7;

    float ar[ALD], wr[WLD];
    #pragma unroll
    for (int j=0;j<ALD;j+=4) *(float4*)&ar[j] = *(const float4*)(Ap + j);
    #pragma unroll
    for (int j=0;j<WLD;j+=4) *(float4*)&wr[j] = *(const float4*)(Wp + j);
    #pragma unroll
    for (int j=0;j<ALD;j++){
        int k = alc+j, k8 = k>>3, kk = k&7, ktg = kk&3, khi = kk>>2;
        As[0][k8][a_mt][(a_g*4+ktg)*4 + a_rhi + khi*2] = f2tf(ar[j]);
    }
    #pragma unroll
    for (int j=0;j<WLD;j++){
        int k = wlc+j, k8 = k>>3, kk = k&7, ktg = kk&3, khi = kk>>2;
        Ws[0][k8][w_nt][(w_g*4+ktg)*2 + khi] = f2tf(wr[j]);
    }
    __syncthreads();

    float c[2][4][4] = {};
    int buf = 0;
    for (int kt = 0;;){
        const bool more = (kt + BK) < KDIM;
        if (more){
            #pragma unroll
            for (int j=0;j<ALD;j+=4) *(float4*)&ar[j] = *(const float4*)(Ap + kt + BK + j);
            #pragma unroll
            for (int j=0;j<WLD;j+=4) *(float4*)&wr[j] = *(const float4*)(Wp + kt + BK + j);
        }
        #pragma unroll
        for (int k8=0; k8<K8; k8++){
            unsigned a[2][4], b[4][2];
            #pragma unroll
            for (int mf=0;mf<2;mf++)
                *(uint4*)a[mf] = *(const uint4*)&As[buf][k8][wm*2+mf][lane*4];
            #pragma unroll
            for (int nf=0;nf<4;nf++)
                *(uint2*)b[nf] = *(const uint2*)&Ws[buf][k8][wn*4+nf][lane*2];
            #pragma unroll
            for (int mf=0;mf<2;mf++)
                #pragma unroll
                for (int nf=0;nf<4;nf++)
                    mma_tf32(c[mf][nf], a[mf], b[nf]);
        }
        if (!more) break;
        #pragma unroll
        for (int j=0;j<ALD;j++){
            int k = alc+j, k8 = k>>3, kk = k&7, ktg = kk&3, khi = kk>>2;
            As[buf^1][k8][a_mt][(a_g*4+ktg)*4 + a_rhi + khi*2] = f2tf(ar[j]);
        }
        #pragma unroll
        for (int j=0;j<WLD;j++){
            int k = wlc+j, k8 = k>>3, kk = k&7, ktg = kk&3, khi = kk>>2;
            Ws[buf^1][k8][w_nt][(w_g*4+ktg)*2 + khi] = f2tf(wr[j]);
        }
        __syncthreads();
        buf ^= 1; kt += BK;
    }

    #pragma unroll
    for (int mf=0;mf<2;mf++){
        #pragma unroll
        for (int nf=0;nf<4;nf++){
            int row = m0 + wm*32 + mf*16 + g;
            int col = n0 + wn*32 + nf*8 + 2*tg;
            #pragma unroll
            for (int hh=0; hh<2; hh++){
                int r = row + hh*8;
                float v0 = c[mf][nf][hh*2+0];
                float v1 = c[mf][nf][hh*2+1];
                if (MODE==0){
                    if (col < DI){
                        g_xssm[(size_t)r*DI + col]   = v0;
                        g_xssm[(size_t)r*DI + col+1] = v1;
                    } else {
                        g_z[(size_t)r*DI + col-DI]   = siluf(v0);
                        g_z[(size_t)r*DI + col-DI+1] = siluf(v1);
                    }
                } else if (MODE==1){
                    outp[(size_t)r*DM + col]   = v0;
                    outp[(size_t)r*DM + col+1] = v1;
                } else {
                    g_P[(size_t)r*(KD*CC) + col]   = v0;
                    g_P[(size_t)r*(KD*CC) + col+1] = v1;
                }
            }
        }
    }
}

// ---------------- conv1d depthwise (k=4, pad 1/2) + silu ----------------
__global__ __launch_bounds__(512) void conv_silu(const float* __restrict__ cw,
                                                 const float* __restrict__ cb){
    const int d  = threadIdx.x;
    const int b  = blockIdx.y;
    const int l0 = blockIdx.x * 32;
    const float w0=cw[d*4+0], w1=cw[d*4+1], w2=cw[d*4+2], w3=cw[d*4+3], bias=cb[d];
    const float* src = g_xssm + (size_t)b*Lseq*DI + d;
    float xm1 = (l0>0)   ? src[(size_t)(l0-1)*DI] : 0.f;
    float x0  =            src[(size_t)(l0  )*DI];
    float xp1 =            src[(size_t)(l0+1)*DI];
    #pragma unroll 4
    for (int l=l0; l<l0+32; l++){
        float xp2 = (l+2 < Lseq) ? src[(size_t)(l+2)*DI] : 0.f;
        float v = w0*xm1 + w1*x0 + w2*xp1 + w3*xp2 + bias;
        g_xcT[((size_t)b*Lseq + l)*DI + d] = siluf(v);
        xm1=x0; x0=xp1; xp1=xp2;
    }
}

// ---------------- scan helpers ----------------
__device__ __forceinline__ int lam_of(int l, int k){
    switch(k){
        case 0:  return l;
        case 1:  return Lseq-1-l;
        case 2:  return (l < Lseq/2) ? 2*l     : 2*(l-Lseq/2)+1;
        default: return (l < Lseq/2) ? 2*l + 1 : 2*(l-Lseq/2);
    }
}
__device__ __forceinline__ float softplusf(float x){
    float e0 = __expf(-fabsf(x));
    return fmaxf(x, 0.f) + __logf(1.f + e0);
}
__device__ __forceinline__ void powchain2(float e1, ull (&pw)[8]){
    float e2=e1*e1, e4=e2*e2, e8=e4*e4;
    ull d2=pk2(e2,e2), d4=pk2(e4,e4), d8=pk2(e8,e8);
    pw[0]=pk2(e1,e2);
    pw[1]=mul2(pw[0],d2);
    pw[2]=mul2(pw[0],d4);
    pw[3]=mul2(pw[1],d4);
    pw[4]=mul2(pw[0],d8);
    pw[5]=mul2(pw[1],d8);
    pw[6]=mul2(pw[2],d8);
    pw[7]=mul2(pw[3],d8);
}

// ---------------- chain flag kernel (one block) ----------------
__global__ __launch_bounds__(256) void chain_flag_kernel(const float* __restrict__ A_logs){
    int ok = 1;
    for (int i = threadIdx.x; i < KD*DI; i += 256){
        const float* al = A_logs + (size_t)i*DS;
        float a0 = -__expf(al[0]);
        #pragma unroll
        for (int n=1;n<16;n++){
            float an = -__expf(al[n]);
            float expect = a0 * (float)(n+1);
            if (fabsf(an-expect) > 1e-4f*fabsf(expect) + 1e-30f) ok = 0;
        }
    }
    ok = __syncthreads_and(ok);
    if (threadIdx.x == 0) g_chainflag = ok;
}

// dt-dot with two independent accumulators (serial depth 4)
__device__ __forceinline__ float dtdot(const float4* r4, const ull (&dtw2)[8], float bias){
    float4 f0=r4[0], f1=r4[1], f2=r4[2], f3=r4[3];
    ull xa = pk2(bias, 0.f);
    ull xb = 0ull;
    xa = fma2(dtw2[0], pk2(f0.x,f0.y), xa);
    xb = fma2(dtw2[1], pk2(f0.z,f0.w), xb);
    xa = fma2(dtw2[2], pk2(f1.x,f1.y), xa);
    xb = fma2(dtw2[3], pk2(f1.z,f1.w), xb);
    xa = fma2(dtw2[4], pk2(f2.x,f2.y), xa);
    xb = fma2(dtw2[5], pk2(f2.z,f2.w), xb);
    xa = fma2(dtw2[6], pk2(f3.x,f3.y), xa);
    xb = fma2(dtw2[7], pk2(f3.z,f3.w), xb);
    ull x2 = add2(xa, xb);
    float xl,xh; upk2(x2,xl,xh);
    return xl + xh;
}

// ---------------- scan phase 1: chain version ----------------
__global__ __launch_bounds__(128, 7)
void scan_part1_chain(const float* __restrict__ dt_proj_w,
                      const float* __restrict__ dt_bias,
                      const float* __restrict__ A_logs){
    if (g_chainflag == 0) return;
    const int tid = threadIdx.x;
    const int d   = blockIdx.x*128 + tid;
    const int ch  = blockIdx.y;
    const int bk  = blockIdx.z;
    const int b   = bk >> 2, kd = bk & 3;

    const float a0 = -__expf(A_logs[((size_t)kd*DI + d)*DS]);
    ull dtw2[8];
    {
        const float4* p = (const float4*)&dt_proj_w[((size_t)kd*DI + d)*DR];
        #pragma unroll
        for (int q=0;q<4;q++){
            float4 v = p[q];
            dtw2[2*q]   = pk2(v.x, v.y);
            dtw2[2*q+1] = pk2(v.z, v.w);
        }
    }
    const float bias = dt_bias[kd*DI + d];

    __shared__ int slam[LC];
    __shared__ alignas(16) float sP[LC*32];
    if (tid < LC) slam[tid] = lam_of(ch*LC + tid, kd);
    __syncthreads();
    {
        const float4* Pb4 = (const float4*)(g_P + (size_t)b*Lseq*(KD*CC) + kd*CC);
        float4* sP4 = (float4*)sP;
        #pragma unroll
        for (int s = tid; s < LC*8; s += 128){
            int st = s >> 3, q = s & 7;
            sP4[s] = Pb4[(size_t)slam[st]*ROW4 + q];
        }
    }
    __syncthreads();

    const float* Ub = g_xcT + (size_t)b*Lseq*DI + d;
    float2* DUE = g_due1 + ((size_t)bk*Lseq + ch*LC)*DI + d;

    ull h2[8];
    #pragma unroll
    for (int j=0;j<8;j++) h2[j]=0ull;
    float S = 0.f;
    float u_next = Ub[(size_t)slam[0]*DI];
    for (int st=0; st<LC; st++){
        float u = u_next;
        u_next = Ub[(size_t)slam[min(st+1, LC-1)]*DI];
        const float4* r4 = (const float4*)(sP + st*32);
        float delta = softplusf(dtdot(r4, dtw2, bias));
        S += delta;
        float e1 = __expf(delta*a0);
        ull pw[8]; powchain2(e1, pw);
        float du = delta * u;
        DUE[(size_t)st*DI] = make_float2(du, e1);
        ull du2 = pk2(du,du);
        float4 b0=r4[4], b1=r4[5], b2=r4[6], b3=r4[7];
        h2[0] = fma2(h2[0], pw[0], mul2(du2, pk2(b0.x,b0.y)));
        h2[1] = fma2(h2[1], pw[1], mul2(du2, pk2(b0.z,b0.w)));
        h2[2] = fma2(h2[2], pw[2], mul2(du2, pk2(b1.x,b1.y)));
        h2[3] = fma2(h2[3], pw[3], mul2(du2, pk2(b1.z,b1.w)));
        h2[4] = fma2(h2[4], pw[4], mul2(du2, pk2(b2.x,b2.y)));
        h2[5] = fma2(h2[5], pw[5], mul2(du2, pk2(b2.z,b2.w)));
        h2[6] = fma2(h2[6], pw[6], mul2(du2, pk2(b3.x,b3.y)));
        h2[7] = fma2(h2[7], pw[7], mul2(du2, pk2(b3.z,b3.w)));
    }
    size_t base = (((size_t)bk*NCH + ch)*DI + d);
    float4* ho = (float4*)&g_hout[base*DS];
    #pragma unroll
    for (int q=0;q<4;q++){
        float l0,h0,l1,h1;
        upk2(h2[2*q],l0,h0); upk2(h2[2*q+1],l1,h1);
        ho[q] = make_float4(l0,h0,l1,h1);
    }
    g_S[base] = S;
}

// ---------------- scan phase 1: generic fallback (grid-stride) ----------------
__global__ __launch_bounds__(128, 2)
void scan_part1_gen(const float* __restrict__ dt_proj_w,
                    const float* __restrict__ dt_bias,
                    const float* __restrict__ A_logs){
    if (g_chainflag != 0) return;
    const int tid = threadIdx.x;
    __shared__ int slam[LC];
    __shared__ alignas(16) float sP[LC*32];
    for (int t = blockIdx.x; t < 4*NCH*32; t += gridDim.x){
        const int xb = t & 3;
        const int ch = (t >> 2) & (NCH-1);
        const int bk = t >> 7;
        const int d  = xb*128 + tid;
        const int b  = bk >> 2, kd = bk & 3;

        float dtw[16], a[16];
        {
            const float4* p = (const float4*)&dt_proj_w[((size_t)kd*DI + d)*DR];
            #pragma unroll
            for (int q=0;q<4;q++){ float4 v=p[q]; dtw[4*q]=v.x; dtw[4*q+1]=v.y; dtw[4*q+2]=v.z; dtw[4*q+3]=v.w; }
            const float* al = &A_logs[((size_t)kd*DI + d)*DS];
            #pragma unroll
            for (int n=0;n<16;n++) a[n] = -__expf(al[n]);
        }
        const float bias = dt_bias[kd*DI + d];

        if (tid < LC) slam[tid] = lam_of(ch*LC + tid, kd);
        __syncthreads();
        const float4* Pb4 = (const float4*)(g_P + (size_t)b*Lseq*(KD*CC) + kd*CC);
        float4* sP4 = (float4*)sP;
        for (int s = tid; s < LC*8; s += 128){
            int st = s >> 3, q = s & 7;
            sP4[s] = Pb4[(size_t)slam[st]*ROW4 + q];
        }
        __syncthreads();

        const float* Ub = g_xcT + (size_t)b*Lseq*DI + d;
        float h[16]; float S=0.f;
        #pragma unroll
        for (int n=0;n<16;n++) h[n]=0.f;
        for (int st = 0; st < LC; st++){
            const float* row = &sP[st*32];
            float x = bias;
            #pragma unroll
            for (int r=0;r<16;r++) x = fmaf(dtw[r], row[r], x);
            float delta = softplusf(x);
            S += delta;
            float du = delta * Ub[(size_t)slam[st]*DI];
            #pragma unroll
            for (int n=0;n<16;n++) h[n] = fmaf(h[n], __expf(delta*a[n]), du * row[16+n]);
        }
        size_t base = (((size_t)bk*NCH + ch)*DI + d);
        #pragma unroll
        for (int n=0;n<16;n++) g_hout[base*DS + n] = h[n];
        g_S[base] = S;
        __syncthreads();
    }
}

// ---------------- scan phase 2: compose chunk boundary states ----------------
__global__ __launch_bounds__(256) void scan_combine(const float* __restrict__ A_logs){
    int t = blockIdx.x*256 + threadIdx.x;
    int n  = t & 15;
    int d  = (t >> 4) & (DI-1);
    int bk = t >> 13;
    int kd = bk & 3;
    float a_n = -__expf(A_logs[((size_t)kd*DI + d)*DS + n]);
    float hin = 0.f;
    for (int c=0; c<NCH; c++){
        size_t base = (((size_t)bk*NCH + c)*DI + d);
        g_hin[base*DS + n] = hin;
        float S = g_S[base];
        hin = fmaf(hin, __expf(a_n*S), g_hout[base*DS + n]);
    }
}

// ---------------- scan phase 3: chain version (consumes du/e1) ----------------
__global__ __launch_bounds__(128, 8)
void scan_part3_chain(){
    if (g_chainflag == 0) return;
    const int tid = threadIdx.x;
    const int d   = blockIdx.x*128 + tid;
    const int ch  = blockIdx.y;
    const int bk  = blockIdx.z;
    const int b   = bk >> 2, kd = bk & 3;

    __shared__ int slam[LC];
    __shared__ alignas(16) float sP[LC*32];   // B,C only
    if (tid < LC) slam[tid] = lam_of(ch*LC + tid, kd);
    __syncthreads();
    {
        const float4* Pb4 = (const float4*)(g_P + (size_t)b*Lseq*(KD*CC) + kd*CC);
        float4* sP4 = (float4*)sP;
        #pragma unroll
        for (int s = tid; s < LC*8; s += 128){
            int st = s >> 3, q = s & 7;
            sP4[s] = Pb4[(size_t)slam[st]*ROW4 + 4 + q];  // floats 16..47 (B,C)
        }
    }
    __syncthreads();

    size_t base = (((size_t)bk*NCH + ch)*DI + d);
    ull h2[8];
    {
        const float4* hi4 = (const float4*)&g_hin[base*DS];
        #pragma unroll
        for (int q=0;q<4;q++){
            float4 v = hi4[q];
            h2[2*q]   = pk2(v.x, v.y);
            h2[2*q+1] = pk2(v.z, v.w);
        }
    }
    const float2* DUE = g_due1 + ((size_t)bk*Lseq + ch*LC)*DI + d;
    float* Yb = g_ydir + (((size_t)kd*Bsz + b)*Lseq)*DI + d;

    float2 de_n = DUE[0];
    for (int st=0; st<LC; st++){
        float2 de = de_n;
        int nx = min(st+1, LC-1);
        de_n = DUE[(size_t)nx*DI];
        ull pw[8]; powchain2(de.y, pw);
        ull du2 = pk2(de.x, de.x);
        const float4* r4 = (const float4*)(sP + st*32);
        float4 b0=r4[0], b1=r4[1], b2=r4[2], b3=r4[3];
        h2[0] = fma2(h2[0], pw[0], mul2(du2, pk2(b0.x,b0.y)));
        h2[1] = fma2(h2[1], pw[1], mul2(du2, pk2(b0.z,b0.w)));
        h2[2] = fma2(h2[2], pw[2], mul2(du2, pk2(b1.x,b1.y)));
        h2[3] = fma2(h2[3], pw[3], mul2(du2, pk2(b1.z,b1.w)));
        h2[4] = fma2(h2[4], pw[4], mul2(du2, pk2(b2.x,b2.y)));
        h2[5] = fma2(h2[5], pw[5], mul2(du2, pk2(b2.z,b2.w)));
        h2[6] = fma2(h2[6], pw[6], mul2(du2, pk2(b3.x,b3.y)));
        h2[7] = fma2(h2[7], pw[7], mul2(du2, pk2(b3.z,b3.w)));
        float4 c0=r4[4], c1=r4[5], c2=r4[6], c3=r4[7];
        ull ya = 0ull, yb = 0ull;
        ya = fma2(h2[0], pk2(c0.x,c0.y), ya);
        yb = fma2(h2[1], pk2(c0.z,c0.w), yb);
        ya = fma2(h2[2], pk2(c1.x,c1.y), ya);
        yb = fma2(h2[3], pk2(c1.z,c1.w), yb);
        ya = fma2(h2[4], pk2(c2.x,c2.y), ya);
        yb = fma2(h2[5], pk2(c2.z,c2.w), yb);
        ya = fma2(h2[6], pk2(c3.x,c3.y), ya);
        yb = fma2(h2[7], pk2(c3.z,c3.w), yb);
        ull y2 = add2(ya, yb);
        float yl,yh; upk2(y2,yl,yh);
        Yb[(size_t)slam[st]*DI] = yl + yh;
    }
}

// ---------------- scan phase 3: generic fallback (grid-stride) ----------------
__global__ __launch_bounds__(128, 2)
void scan_part3_gen(const float* __restrict__ dt_proj_w,
                    const float* __restrict__ dt_bias,
                    const float* __restrict__ A_logs){
    if (g_chainflag != 0) return;
    const int tid = threadIdx.x;
    __shared__ int slam[LC];
    __shared__ alignas(16) float sP[LC*48];
    for (int t = blockIdx.x; t < 4*NCH*32; t += gridDim.x){
        const int xb = t & 3;
        const int ch = (t >> 2) & (NCH-1);
        const int bk = t >> 7;
        const int d  = xb*128 + tid;
        const int b  = bk >> 2, kd = bk & 3;

        float dtw[16], a[16];
        {
            const float4* p = (const float4*)&dt_proj_w[((size_t)kd*DI + d)*DR];
            #pragma unroll
            for (int q=0;q<4;q++){ float4 v=p[q]; dtw[4*q]=v.x; dtw[4*q+1]=v.y; dtw[4*q+2]=v.z; dtw[4*q+3]=v.w; }
            const float* al = &A_logs[((size_t)kd*DI + d)*DS];
            #pragma unroll
            for (int n=0;n<16;n++) a[n] = -__expf(al[n]);
        }
        const float bias = dt_bias[kd*DI + d];

        if (tid < LC) slam[tid] = lam_of(ch*LC + tid, kd);
        __syncthreads();
        const float4* Pb4 = (const float4*)(g_P + (size_t)b*Lseq*(KD*CC) + kd*CC);
        float4* sP4 = (float4*)sP;
        for (int s = tid; s < LC*12; s += 128){
            int st = s / 12, q = s - st*12;
            sP4[s] = Pb4[(size_t)slam[st]*ROW4 + q];
        }
        __syncthreads();

        size_t base = (((size_t)bk*NCH + ch)*DI + d);
        float h[16];
        #pragma unroll
        for (int n=0;n<16;n++) h[n] = g_hin[base*DS + n];
        const float* Ub = g_xcT + (size_t)b*Lseq*DI + d;
        float* Yb = g_ydir + (((size_t)kd*Bsz + b)*Lseq)*DI + d;
        for (int st = 0; st < LC; st++){
            const float* row = &sP[st*48];
            float x = bias;
            #pragma unroll
            for (int r=0;r<16;r++) x = fmaf(dtw[r], row[r], x);
            float delta = softplusf(x);
            float u  = Ub[(size_t)slam[st]*DI];
            float du = delta * u;
            float y = 0.f;
            #pragma unroll
            for (int n=0;n<16;n++){
                h[n] = fmaf(h[n], __expf(delta*a[n]), du * row[16+n]);
                y = fmaf(h[n], row[32+n], y);
            }
            Yb[(size_t)slam[st]*DI] = y;
        }
        __syncthreads();
    }
}

// ---------------- layernorm * ln_g + ln_b, gated by silu(z); adds sumD*xc ----------------
__global__ __launch_bounds__(128) void norm_kernel(const float* __restrict__ ln_g,
                                                   const float* __restrict__ ln_b,
                                                   const float* __restrict__ Ds){
    const int row = blockIdx.x;
    const int tid = threadIdx.x;
    const float* z = g_z + (size_t)row*DI;
    const float4* y0 = (const float4*)(g_ydir + (size_t)row*DI);
    const float4* y1 = (const float4*)(g_ydir + (size_t)(Bsz*Lseq + row)*DI);
    const float4* y2 = (const float4*)(g_ydir + (size_t)(2*Bsz*Lseq + row)*DI);
    const float4* y3 = (const float4*)(g_ydir + (size_t)(3*Bsz*Lseq + row)*DI);
    const float4* xc = (const float4*)(g_xcT + (size_t)row*DI);

    float4 sd;
    {
        const float4* D0 = (const float4*)(Ds);
        const float4* D1 = (const float4*)(Ds + DI);
        const float4* D2 = (const float4*)(Ds + 2*DI);
        const float4* D3 = (const float4*)(Ds + 3*DI);
        float4 q0=D0[tid], q1=D1[tid], q2=D2[tid], q3=D3[tid];
        sd = make_float4(q0.x+q1.x+q2.x+q3.x, q0.y+q1.y+q2.y+q3.y,
                         q0.z+q1.z+q2.z+q3.z, q0.w+q1.w+q2.w+q3.w);
    }

    float4 a0 = y0[tid], a1 = y1[tid], a2 = y2[tid], a3 = y3[tid];
    float4 xv = xc[tid];
    float4 v = make_float4(a0.x+a1.x+a2.x+a3.x + sd.x*xv.x,
                           a0.y+a1.y+a2.y+a3.y + sd.y*xv.y,
                           a0.z+a1.z+a2.z+a3.z + sd.z*xv.z,
                           a0.w+a1.w+a2.w+a3.w + sd.w*xv.w);
    float s  = v.x+v.y+v.z+v.w;
    float sq = v.x*v.x + v.y*v.y + v.z*v.z + v.w*v.w;
    #pragma unroll
    for (int o=16;o>0;o>>=1){
        s  += __shfl_xor_sync(0xffffffffu, s,  o);
        sq += __shfl_xor_sync(0xffffffffu, sq, o);
    }
    __shared__ float ss[4], sqq[4];
    const int wid = tid >> 5, lane = tid & 31;
    if (lane==0){ ss[wid]=s; sqq[wid]=sq; }
    __syncthreads();
    s  = ss[0]+ss[1]+ss[2]+ss[3];
    sq = sqq[0]+sqq[1]+sqq[2]+sqq[3];
    const float mu  = s * (1.f/512.f);
    const float var = sq * (1.f/512.f) - mu*mu;
    const float rs  = rsqrtf(var + 1e-5f);

    float4 g4 = ((const float4*)ln_g)[tid];
    float4 b4 = ((const float4*)ln_b)[tid];
    float4 z4 = ((const float4*)z)[tid];
    v.x = ((v.x-mu)*rs*g4.x + b4.x) * z4.x;
    v.y = ((v.y-mu)*rs*g4.y + b4.y) * z4.y;
    v.z = ((v.z-mu)*rs*g4.z + b4.z) * z4.z;
    v.w = ((v.w-mu)*rs*g4.w + b4.w) * z4.w;
    ((float4*)(g_ysum + (size_t)row*DI))[tid] = v;
}

// ---------------- launch ----------------
extern "C" void kernel_launch(void* const* d_in, const int* in_sizes, int n_in,
                              void* d_out, int out_size){
    const float* x          = (const float*)d_in[0];
    const float* in_proj_w  = (const float*)d_in[1];
    const float* conv_w     = (const float*)d_in[2];
    const float* conv_b     = (const float*)d_in[3];
    const float* x_proj_w   = (const float*)d_in[4];
    const float* dt_proj_w  = (const float*)d_in[5];
    const float* dt_bias    = (const float*)d_in[6];
    const float* A_logs     = (const float*)d_in[7];
    const float* Ds         = (const float*)d_in[8];
    const float* ln_g       = (const float*)d_in[9];
    const float* ln_b       = (const float*)d_in[10];
    const float* out_proj_w = (const float*)d_in[11];
    float* out = (float*)d_out;

    chain_flag_kernel        <<<1, 256>>>(A_logs);
    gemm_tc<256,0,128,16>    <<<dim3(64,16), 256>>>(x, in_proj_w, nullptr);
    conv_silu                <<<dim3(32, 8), 512>>>(conv_w, conv_b);
    gemm_tc<512,2, 64,32>    <<<dim3(128,3), 128>>>(nullptr, x_proj_w, nullptr);
    scan_part1_chain         <<<dim3(4, NCH, 32), 128>>>(dt_proj_w, dt_bias, A_logs);
    scan_part1_gen           <<<592, 128>>>(dt_proj_w, dt_bias, A_logs);
    scan_combine             <<<1024, 256>>>(A_logs);
    scan_part3_chain         <<<dim3(4, NCH, 32), 128>>>();
    scan_part3_gen           <<<592, 128>>>(dt_proj_w, dt_bias, A_logs);
    norm_kernel              <<<8192, 128>>>(ln_g, ln_b, Ds);
    gemm_tc<512,1,128,16>    <<<dim3(64, 4), 256>>>(nullptr, out_proj_w, out);
}

// round 16
// speedup vs baseline: 1.0577x; 1.0577x over previous
#include <cuda_runtime.h>
#include <cuda_bf16.h>

// ---------------- problem constants ----------------
constexpr int Bsz  = 8;
constexpr int Lseq = 1024;
constexpr int DM   = 256;   // d_model
constexpr int DI   = 512;   // d_inner
constexpr int DS   = 16;    // d_state
constexpr int DR   = 16;    // dt_rank
constexpr int KD   = 4;     // directions
constexpr int CC   = DR + 2*DS;  // 48
constexpr int NCH  = 32;    // scan chunks
constexpr int LC   = Lseq/NCH;   // 32 steps per chunk
constexpr int ROW4 = (KD*CC)/4;  // 48 float4 per (b,lam) row of g_P

// ---------------- scratch (device globals; no allocation) ----------------
__device__ float g_xssm[Bsz*Lseq*DI];
__device__ float g_z   [Bsz*Lseq*DI];
__device__ float g_xcT [Bsz*Lseq*DI];
__device__ float g_P   [Bsz*Lseq*KD*CC];
__device__ float g_ysum[Bsz*Lseq*DI];
__device__ float g_ydir[KD*Bsz*Lseq*DI];
__device__ float g_hout[Bsz*KD*NCH*DI*DS];
__device__ float g_hin [Bsz*KD*NCH*DI*DS];
__device__ float g_S   [Bsz*KD*NCH*DI];
__device__ float2 g_due1[(size_t)KD*Bsz*Lseq*DI];   // (du, e1) per step
__device__ int    g_chainflag;

__device__ __forceinline__ float siluf(float v){
    return v * (1.0f / (1.0f + __expf(-v)));
}
__device__ __forceinline__ unsigned f2tf(float f){
    unsigned u; asm("cvt.rna.tf32.f32 %0, %1;" : "=r"(u) : "f"(f)); return u;
}
__device__ __forceinline__ void mma_tf32(float (&c)[4], const unsigned (&a)[4], const unsigned (&b)[2]){
    asm volatile(
        "mma.sync.aligned.m16n8k8.row.col.f32.tf32.tf32.f32 "
        "{%0,%1,%2,%3}, {%4,%5,%6,%7}, {%8,%9}, {%0,%1,%2,%3};\n"
        : "+f"(c[0]), "+f"(c[1]), "+f"(c[2]), "+f"(c[3])
        : "r"(a[0]), "r"(a[1]), "r"(a[2]), "r"(a[3]), "r"(b[0]), "r"(b[1]));
}

// -------- packed f32x2 helpers --------
typedef unsigned long long ull;
__device__ __forceinline__ ull pk2(float lo, float hi){
    ull r; asm("mov.b64 %0, {%1,%2};" : "=l"(r) : "f"(lo), "f"(hi)); return r;
}
__device__ __forceinline__ void upk2(ull v, float& lo, float& hi){
    asm("mov.b64 {%0,%1}, %2;" : "=f"(lo), "=f"(hi) : "l"(v));
}
__device__ __forceinline__ ull fma2(ull a, ull b, ull c){
    ull d; asm("fma.rn.f32x2 %0, %1, %2, %3;" : "=l"(d) : "l"(a), "l"(b), "l"(c)); return d;
}
__device__ __forceinline__ ull mul2(ull a, ull b){
    ull d; asm("mul.rn.f32x2 %0, %1, %2;" : "=l"(d) : "l"(a), "l"(b)); return d;
}
__device__ __forceinline__ ull add2(ull a, ull b){
    ull d; asm("add.rn.f32x2 %0, %1, %2;" : "=l"(d) : "l"(a), "l"(b)); return d;
}

// ---------------- tf32 tensor-core GEMM, double-buffered (R12 config) ----------------
// MODE 0: A=x (Mx256), W=in_proj_w; split -> g_xssm / silu -> g_z   (BM=128)
// MODE 1: A=g_ysum (Mx512), W=out_proj_w; write outp (Mx256)        (BM=128)
// MODE 2: A=g_xcT (Mx512), W=x_proj_w (192x512); write g_P (Mx192)  (BM=64)
template<int KDIM, int MODE, int BM>
__global__ __launch_bounds__(BM==128?256:128, BM==128?2:4)
void gemm_tc(const float* __restrict__ Ain,
             const float* __restrict__ W,
             float* __restrict__ outp){
    constexpr int BN=64, BK=16;
    constexpr int AP=BM+4, WP=BN+4;
    constexpr int WM   = BM/32;
    constexpr int WREG = (BM==128)?4:8;
    __shared__ unsigned As[2][BK][AP];
    __shared__ unsigned Ws[2][BK][WP];
    const float* A = (MODE==0) ? Ain : (MODE==1 ? (const float*)g_ysum : (const float*)g_xcT);
    const int m0 = blockIdx.x*BM, n0 = blockIdx.y*BN;
    const int tid = threadIdx.x;
    const int wid = tid>>5, lane = tid&31;
    const int wm = wid % WM, wn = wid / WM;
    const int g = lane>>2, tg = lane&3;

    const int alr = tid>>1, alc = (tid&1)*8;
    const int wlr = (BM==128) ? (tid>>2) : (tid>>1);
    const int wlc = (BM==128) ? (tid&3)*4 : (tid&1)*8;

    const float* Ap = A + (size_t)(m0+alr)*KDIM + alc;
    const float* Wp = W + (size_t)(n0+wlr)*KDIM + wlc;

    float ar[8], wr[WREG];
    *(float4*)&ar[0] = *(const float4*)(Ap);
    *(float4*)&ar[4] = *(const float4*)(Ap+4);
    *(float4*)&wr[0] = *(const float4*)(Wp);
    if (WREG==8) *(float4*)&wr[4] = *(const float4*)(Wp+4);
    #pragma unroll
    for (int j=0;j<8;j++)    As[0][alc+j][alr] = f2tf(ar[j]);
    #pragma unroll
    for (int j=0;j<WREG;j++) Ws[0][wlc+j][wlr] = f2tf(wr[j]);
    __syncthreads();

    float c[2][4][4] = {};
    int buf = 0;
    for (int kt = 0;;){
        const bool more = (kt + BK) < KDIM;
        if (more){
            *(float4*)&ar[0] = *(const float4*)(Ap + kt + BK);
            *(float4*)&ar[4] = *(const float4*)(Ap + kt + BK + 4);
            *(float4*)&wr[0] = *(const float4*)(Wp + kt + BK);
            if (WREG==8) *(float4*)&wr[4] = *(const float4*)(Wp + kt + BK + 4);
        }
        #pragma unroll
        for (int ks=0; ks<BK; ks+=8){
            unsigned a[2][4], b[4][2];
            #pragma unroll
            for (int mf=0;mf<2;mf++){
                int r = wm*32 + mf*16;
                a[mf][0]=As[buf][ks+tg  ][r+g  ];
                a[mf][1]=As[buf][ks+tg  ][r+g+8];
                a[mf][2]=As[buf][ks+tg+4][r+g  ];
                a[mf][3]=As[buf][ks+tg+4][r+g+8];
            }
            #pragma unroll
            for (int nf=0;nf<4;nf++){
                int n = wn*32 + nf*8;
                b[nf][0]=Ws[buf][ks+tg  ][n+g];
                b[nf][1]=Ws[buf][ks+tg+4][n+g];
            }
            #pragma unroll
            for (int mf=0;mf<2;mf++)
                #pragma unroll
                for (int nf=0;nf<4;nf++)
                    mma_tf32(c[mf][nf], a[mf], b[nf]);
        }
        if (!more) break;
        #pragma unroll
        for (int j=0;j<8;j++)    As[buf^1][alc+j][alr] = f2tf(ar[j]);
        #pragma unroll
        for (int j=0;j<WREG;j++) Ws[buf^1][wlc+j][wlr] = f2tf(wr[j]);
        __syncthreads();
        buf ^= 1; kt += BK;
    }

    #pragma unroll
    for (int mf=0;mf<2;mf++){
        #pragma unroll
        for (int nf=0;nf<4;nf++){
            int row = m0 + wm*32 + mf*16 + g;
            int col = n0 + wn*32 + nf*8 + 2*tg;
            #pragma unroll
            for (int hh=0; hh<2; hh++){
                int r = row + hh*8;
                float v0 = c[mf][nf][hh*2+0];
                float v1 = c[mf][nf][hh*2+1];
                if (MODE==0){
                    if (col < DI){
                        g_xssm[(size_t)r*DI + col]   = v0;
                        g_xssm[(size_t)r*DI + col+1] = v1;
                    } else {
                        g_z[(size_t)r*DI + col-DI]   = siluf(v0);
                        g_z[(size_t)r*DI + col-DI+1] = siluf(v1);
                    }
                } else if (MODE==1){
                    outp[(size_t)r*DM + col]   = v0;
                    outp[(size_t)r*DM + col+1] = v1;
                } else {
                    g_P[(size_t)r*(KD*CC) + col]   = v0;
                    g_P[(size_t)r*(KD*CC) + col+1] = v1;
                }
            }
        }
    }
}

// ---------------- conv1d depthwise (k=4, pad 1/2) + silu ----------------
__global__ __launch_bounds__(512) void conv_silu(const float* __restrict__ cw,
                                                 const float* __restrict__ cb){
    const int d  = threadIdx.x;
    const int b  = blockIdx.y;
    const int l0 = blockIdx.x * 32;
    const float w0=cw[d*4+0], w1=cw[d*4+1], w2=cw[d*4+2], w3=cw[d*4+3], bias=cb[d];
    const float* src = g_xssm + (size_t)b*Lseq*DI + d;
    float xm1 = (l0>0)   ? src[(size_t)(l0-1)*DI] : 0.f;
    float x0  =            src[(size_t)(l0  )*DI];
    float xp1 =            src[(size_t)(l0+1)*DI];
    #pragma unroll 4
    for (int l=l0; l<l0+32; l++){
        float xp2 = (l+2 < Lseq) ? src[(size_t)(l+2)*DI] : 0.f;
        float v = w0*xm1 + w1*x0 + w2*xp1 + w3*xp2 + bias;
        g_xcT[((size_t)b*Lseq + l)*DI + d] = siluf(v);
        xm1=x0; x0=xp1; xp1=xp2;
    }
}

// ---------------- scan helpers ----------------
__device__ __forceinline__ int lam_of(int l, int k){
    switch(k){
        case 0:  return l;
        case 1:  return Lseq-1-l;
        case 2:  return (l < Lseq/2) ? 2*l     : 2*(l-Lseq/2)+1;
        default: return (l < Lseq/2) ? 2*l + 1 : 2*(l-Lseq/2);
    }
}
__device__ __forceinline__ float softplusf(float x){
    float e0 = __expf(-fabsf(x));
    return fmaxf(x, 0.f) + __logf(1.f + e0);
}
__device__ __forceinline__ void powchain2(float e1, ull (&pw)[8]){
    float e2=e1*e1, e4=e2*e2, e8=e4*e4;
    ull d2=pk2(e2,e2), d4=pk2(e4,e4), d8=pk2(e8,e8);
    pw[0]=pk2(e1,e2);
    pw[1]=mul2(pw[0],d2);
    pw[2]=mul2(pw[0],d4);
    pw[3]=mul2(pw[1],d4);
    pw[4]=mul2(pw[0],d8);
    pw[5]=mul2(pw[1],d8);
    pw[6]=mul2(pw[2],d8);
    pw[7]=mul2(pw[3],d8);
}

// ---------------- chain flag kernel (one block) ----------------
__global__ __launch_bounds__(256) void chain_flag_kernel(const float* __restrict__ A_logs){
    int ok = 1;
    for (int i = threadIdx.x; i < KD*DI; i += 256){
        const float* al = A_logs + (size_t)i*DS;
        float a0 = -__expf(al[0]);
        #pragma unroll
        for (int n=1;n<16;n++){
            float an = -__expf(al[n]);
            float expect = a0 * (float)(n+1);
            if (fabsf(an-expect) > 1e-4f*fabsf(expect) + 1e-30f) ok = 0;
        }
    }
    ok = __syncthreads_and(ok);
    if (threadIdx.x == 0) g_chainflag = ok;
}

// dt-dot with two independent accumulators (serial depth 4)
__device__ __forceinline__ float dtdot(const float4* r4, const ull (&dtw2)[8], float bias){
    float4 f0=r4[0], f1=r4[1], f2=r4[2], f3=r4[3];
    ull xa = pk2(bias, 0.f);
    ull xb = 0ull;
    xa = fma2(dtw2[0], pk2(f0.x,f0.y), xa);
    xb = fma2(dtw2[1], pk2(f0.z,f0.w), xb);
    xa = fma2(dtw2[2], pk2(f1.x,f1.y), xa);
    xb = fma2(dtw2[3], pk2(f1.z,f1.w), xb);
    xa = fma2(dtw2[4], pk2(f2.x,f2.y), xa);
    xb = fma2(dtw2[5], pk2(f2.z,f2.w), xb);
    xa = fma2(dtw2[6], pk2(f3.x,f3.y), xa);
    xb = fma2(dtw2[7], pk2(f3.z,f3.w), xb);
    ull x2 = add2(xa, xb);
    float xl,xh; upk2(x2,xl,xh);
    return xl + xh;
}

// ---------------- scan phase 1: chain version ----------------
__global__ __launch_bounds__(128, 7)
void scan_part1_chain(const float* __restrict__ dt_proj_w,
                      const float* __restrict__ dt_bias,
                      const float* __restrict__ A_logs){
    if (g_chainflag == 0) return;
    const int tid = threadIdx.x;
    const int d   = blockIdx.x*128 + tid;
    const int ch  = blockIdx.y;
    const int bk  = blockIdx.z;
    const int b   = bk >> 2, kd = bk & 3;

    const float a0 = -__expf(A_logs[((size_t)kd*DI + d)*DS]);
    ull dtw2[8];
    {
        const float4* p = (const float4*)&dt_proj_w[((size_t)kd*DI + d)*DR];
        #pragma unroll
        for (int q=0;q<4;q++){
            float4 v = p[q];
            dtw2[2*q]   = pk2(v.x, v.y);
            dtw2[2*q+1] = pk2(v.z, v.w);
        }
    }
    const float bias = dt_bias[kd*DI + d];

    __shared__ int slam[LC];
    __shared__ alignas(16) float sP[LC*32];
    if (tid < LC) slam[tid] = lam_of(ch*LC + tid, kd);
    __syncthreads();
    {
        const float4* Pb4 = (const float4*)(g_P + (size_t)b*Lseq*(KD*CC) + kd*CC);
        float4* sP4 = (float4*)sP;
        #pragma unroll
        for (int s = tid; s < LC*8; s += 128){
            int st = s >> 3, q = s & 7;
            sP4[s] = Pb4[(size_t)slam[st]*ROW4 + q];
        }
    }
    __syncthreads();

    const float* Ub = g_xcT + (size_t)b*Lseq*DI + d;
    float2* DUE = g_due1 + ((size_t)bk*Lseq + ch*LC)*DI + d;

    ull h2[8];
    #pragma unroll
    for (int j=0;j<8;j++) h2[j]=0ull;
    float S = 0.f;
    float u_next = Ub[(size_t)slam[0]*DI];
    for (int st=0; st<LC; st++){
        float u = u_next;
        u_next = Ub[(size_t)slam[min(st+1, LC-1)]*DI];
        const float4* r4 = (const float4*)(sP + st*32);
        float delta = softplusf(dtdot(r4, dtw2, bias));
        S += delta;
        float e1 = __expf(delta*a0);
        ull pw[8]; powchain2(e1, pw);
        float du = delta * u;
        DUE[(size_t)st*DI] = make_float2(du, e1);
        ull du2 = pk2(du,du);
        float4 b0=r4[4], b1=r4[5], b2=r4[6], b3=r4[7];
        h2[0] = fma2(h2[0], pw[0], mul2(du2, pk2(b0.x,b0.y)));
        h2[1] = fma2(h2[1], pw[1], mul2(du2, pk2(b0.z,b0.w)));
        h2[2] = fma2(h2[2], pw[2], mul2(du2, pk2(b1.x,b1.y)));
        h2[3] = fma2(h2[3], pw[3], mul2(du2, pk2(b1.z,b1.w)));
        h2[4] = fma2(h2[4], pw[4], mul2(du2, pk2(b2.x,b2.y)));
        h2[5] = fma2(h2[5], pw[5], mul2(du2, pk2(b2.z,b2.w)));
        h2[6] = fma2(h2[6], pw[6], mul2(du2, pk2(b3.x,b3.y)));
        h2[7] = fma2(h2[7], pw[7], mul2(du2, pk2(b3.z,b3.w)));
    }
    size_t base = (((size_t)bk*NCH + ch)*DI + d);
    float4* ho = (float4*)&g_hout[base*DS];
    #pragma unroll
    for (int q=0;q<4;q++){
        float l0,h0,l1,h1;
        upk2(h2[2*q],l0,h0); upk2(h2[2*q+1],l1,h1);
        ho[q] = make_float4(l0,h0,l1,h1);
    }
    g_S[base] = S;
}

// ---------------- scan phase 1: generic fallback (grid-stride) ----------------
__global__ __launch_bounds__(128, 2)
void scan_part1_gen(const float* __restrict__ dt_proj_w,
                    const float* __restrict__ dt_bias,
                    const float* __restrict__ A_logs){
    if (g_chainflag != 0) return;
    const int tid = threadIdx.x;
    __shared__ int slam[LC];
    __shared__ alignas(16) float sP[LC*32];
    for (int t = blockIdx.x; t < 4*NCH*32; t += gridDim.x){
        const int xb = t & 3;
        const int ch = (t >> 2) & (NCH-1);
        const int bk = t >> 7;
        const int d  = xb*128 + tid;
        const int b  = bk >> 2, kd = bk & 3;

        float dtw[16], a[16];
        {
            const float4* p = (const float4*)&dt_proj_w[((size_t)kd*DI + d)*DR];
            #pragma unroll
            for (int q=0;q<4;q++){ float4 v=p[q]; dtw[4*q]=v.x; dtw[4*q+1]=v.y; dtw[4*q+2]=v.z; dtw[4*q+3]=v.w; }
            const float* al = &A_logs[((size_t)kd*DI + d)*DS];
            #pragma unroll
            for (int n=0;n<16;n++) a[n] = -__expf(al[n]);
        }
        const float bias = dt_bias[kd*DI + d];

        if (tid < LC) slam[tid] = lam_of(ch*LC + tid, kd);
        __syncthreads();
        const float4* Pb4 = (const float4*)(g_P + (size_t)b*Lseq*(KD*CC) + kd*CC);
        float4* sP4 = (float4*)sP;
        for (int s = tid; s < LC*8; s += 128){
            int st = s >> 3, q = s & 7;
            sP4[s] = Pb4[(size_t)slam[st]*ROW4 + q];
        }
        __syncthreads();

        const float* Ub = g_xcT + (size_t)b*Lseq*DI + d;
        float h[16]; float S=0.f;
        #pragma unroll
        for (int n=0;n<16;n++) h[n]=0.f;
        for (int st = 0; st < LC; st++){
            const float* row = &sP[st*32];
            float x = bias;
            #pragma unroll
            for (int r=0;r<16;r++) x = fmaf(dtw[r], row[r], x);
            float delta = softplusf(x);
            S += delta;
            float du = delta * Ub[(size_t)slam[st]*DI];
            #pragma unroll
            for (int n=0;n<16;n++) h[n] = fmaf(h[n], __expf(delta*a[n]), du * row[16+n]);
        }
        size_t base = (((size_t)bk*NCH + ch)*DI + d);
        #pragma unroll
        for (int n=0;n<16;n++) g_hout[base*DS + n] = h[n];
        g_S[base] = S;
        __syncthreads();
    }
}

// ---------------- scan phase 2: compose chunk boundary states ----------------
__global__ __launch_bounds__(256) void scan_combine(const float* __restrict__ A_logs){
    int t = blockIdx.x*256 + threadIdx.x;
    int n  = t & 15;
    int d  = (t >> 4) & (DI-1);
    int bk = t >> 13;
    int kd = bk & 3;
    float a_n = -__expf(A_logs[((size_t)kd*DI + d)*DS + n]);
    float hin = 0.f;
    for (int c=0; c<NCH; c++){
        size_t base = (((size_t)bk*NCH + c)*DI + d);
        g_hin[base*DS + n] = hin;
        float S = g_S[base];
        hin = fmaf(hin, __expf(a_n*S), g_hout[base*DS + n]);
    }
}

// ---------------- scan phase 3: chain version (consumes du/e1) ----------------
__global__ __launch_bounds__(128, 8)
void scan_part3_chain(){
    if (g_chainflag == 0) return;
    const int tid = threadIdx.x;
    const int d   = blockIdx.x*128 + tid;
    const int ch  = blockIdx.y;
    const int bk  = blockIdx.z;
    const int b   = bk >> 2, kd = bk & 3;

    __shared__ int slam[LC];
    __shared__ alignas(16) float sP[LC*32];   // B,C only
    if (tid < LC) slam[tid] = lam_of(ch*LC + tid, kd);
    __syncthreads();
    {
        const float4* Pb4 = (const float4*)(g_P + (size_t)b*Lseq*(KD*CC) + kd*CC);
        float4* sP4 = (float4*)sP;
        #pragma unroll
        for (int s = tid; s < LC*8; s += 128){
            int st = s >> 3, q = s & 7;
            sP4[s] = Pb4[(size_t)slam[st]*ROW4 + 4 + q];  // floats 16..47 (B,C)
        }
    }
    __syncthreads();

    size_t base = (((size_t)bk*NCH + ch)*DI + d);
    ull h2[8];
    {
        const float4* hi4 = (const float4*)&g_hin[base*DS];
        #pragma unroll
        for (int q=0;q<4;q++){
            float4 v = hi4[q];
            h2[2*q]   = pk2(v.x, v.y);
            h2[2*q+1] = pk2(v.z, v.w);
        }
    }
    const float2* DUE = g_due1 + ((size_t)bk*Lseq + ch*LC)*DI + d;
    float* Yb = g_ydir + (((size_t)kd*Bsz + b)*Lseq)*DI + d;

    float2 de_n = DUE[0];
    for (int st=0; st<LC; st++){
        float2 de = de_n;
        int nx = min(st+1, LC-1);
        de_n = DUE[(size_t)nx*DI];
        ull pw[8]; powchain2(de.y, pw);
        ull du2 = pk2(de.x, de.x);
        const float4* r4 = (const float4*)(sP + st*32);
        float4 b0=r4[0], b1=r4[1], b2=r4[2], b3=r4[3];
        h2[0] = fma2(h2[0], pw[0], mul2(du2, pk2(b0.x,b0.y)));
        h2[1] = fma2(h2[1], pw[1], mul2(du2, pk2(b0.z,b0.w)));
        h2[2] = fma2(h2[2], pw[2], mul2(du2, pk2(b1.x,b1.y)));
        h2[3] = fma2(h2[3], pw[3], mul2(du2, pk2(b1.z,b1.w)));
        h2[4] = fma2(h2[4], pw[4], mul2(du2, pk2(b2.x,b2.y)));
        h2[5] = fma2(h2[5], pw[5], mul2(du2, pk2(b2.z,b2.w)));
        h2[6] = fma2(h2[6], pw[6], mul2(du2, pk2(b3.x,b3.y)));
        h2[7] = fma2(h2[7], pw[7], mul2(du2, pk2(b3.z,b3.w)));
        float4 c0=r4[4], c1=r4[5], c2=r4[6], c3=r4[7];
        ull ya = 0ull, yb = 0ull;
        ya = fma2(h2[0], pk2(c0.x,c0.y), ya);
        yb = fma2(h2[1], pk2(c0.z,c0.w), yb);
        ya = fma2(h2[2], pk2(c1.x,c1.y), ya);
        yb = fma2(h2[3], pk2(c1.z,c1.w), yb);
        ya = fma2(h2[4], pk2(c2.x,c2.y), ya);
        yb = fma2(h2[5], pk2(c2.z,c2.w), yb);
        ya = fma2(h2[6], pk2(c3.x,c3.y), ya);
        yb = fma2(h2[7], pk2(c3.z,c3.w), yb);
        ull y2 = add2(ya, yb);
        float yl,yh; upk2(y2,yl,yh);
        Yb[(size_t)slam[st]*DI] = yl + yh;
    }
}

// ---------------- scan phase 3: generic fallback (grid-stride) ----------------
__global__ __launch_bounds__(128, 2)
void scan_part3_gen(const float* __restrict__ dt_proj_w,
                    const float* __restrict__ dt_bias,
                    const float* __restrict__ A_logs){
    if (g_chainflag != 0) return;
    const int tid = threadIdx.x;
    __shared__ int slam[LC];
    __shared__ alignas(16) float sP[LC*48];
    for (int t = blockIdx.x; t < 4*NCH*32; t += gridDim.x){
        const int xb = t & 3;
        const int ch = (t >> 2) & (NCH-1);
        const int bk = t >> 7;
        const int d  = xb*128 + tid;
        const int b  = bk >> 2, kd = bk & 3;

        float dtw[16], a[16];
        {
            const float4* p = (const float4*)&dt_proj_w[((size_t)kd*DI + d)*DR];
            #pragma unroll
            for (int q=0;q<4;q++){ float4 v=p[q]; dtw[4*q]=v.x; dtw[4*q+1]=v.y; dtw[4*q+2]=v.z; dtw[4*q+3]=v.w; }
            const float* al = &A_logs[((size_t)kd*DI + d)*DS];
            #pragma unroll
            for (int n=0;n<16;n++) a[n] = -__expf(al[n]);
        }
        const float bias = dt_bias[kd*DI + d];

        if (tid < LC) slam[tid] = lam_of(ch*LC + tid, kd);
        __syncthreads();
        const float4* Pb4 = (const float4*)(g_P + (size_t)b*Lseq*(KD*CC) + kd*CC);
        float4* sP4 = (float4*)sP;
        for (int s = tid; s < LC*12; s += 128){
            int st = s / 12, q = s - st*12;
            sP4[s] = Pb4[(size_t)slam[st]*ROW4 + q];
        }
        __syncthreads();

        size_t base = (((size_t)bk*NCH + ch)*DI + d);
        float h[16];
        #pragma unroll
        for (int n=0;n<16;n++) h[n] = g_hin[base*DS + n];
        const float* Ub = g_xcT + (size_t)b*Lseq*DI + d;
        float* Yb = g_ydir + (((size_t)kd*Bsz + b)*Lseq)*DI + d;
        for (int st = 0; st < LC; st++){
            const float* row = &sP[st*48];
            float x = bias;
            #pragma unroll
            for (int r=0;r<16;r++) x = fmaf(dtw[r], row[r], x);
            float delta = softplusf(x);
            float u  = Ub[(size_t)slam[st]*DI];
            float du = delta * u;
            float y = 0.f;
            #pragma unroll
            for (int n=0;n<16;n++){
                h[n] = fmaf(h[n], __expf(delta*a[n]), du * row[16+n]);
                y = fmaf(h[n], row[32+n], y);
            }
            Yb[(size_t)slam[st]*DI] = y;
        }
        __syncthreads();
    }
}

// ---------------- layernorm * ln_g + ln_b, gated by silu(z); adds sumD*xc ----------------
__global__ __launch_bounds__(128) void norm_kernel(const float* __restrict__ ln_g,
                                                   const float* __restrict__ ln_b,
                                                   const float* __restrict__ Ds){
    const int row = blockIdx.x;
    const int tid = threadIdx.x;
    const float* z = g_z + (size_t)row*DI;
    const float4* y0 = (const float4*)(g_ydir + (size_t)row*DI);
    const float4* y1 = (const float4*)(g_ydir + (size_t)(Bsz*Lseq + row)*DI);
    const float4* y2 = (const float4*)(g_ydir + (size_t)(2*Bsz*Lseq + row)*DI);
    const float4* y3 = (const float4*)(g_ydir + (size_t)(3*Bsz*Lseq + row)*DI);
    const float4* xc = (const float4*)(g_xcT + (size_t)row*DI);

    float4 sd;
    {
        const float4* D0 = (const float4*)(Ds);
        const float4* D1 = (const float4*)(Ds + DI);
        const float4* D2 = (const float4*)(Ds + 2*DI);
        const float4* D3 = (const float4*)(Ds + 3*DI);
        float4 q0=D0[tid], q1=D1[tid], q2=D2[tid], q3=D3[tid];
        sd = make_float4(q0.x+q1.x+q2.x+q3.x, q0.y+q1.y+q2.y+q3.y,
                         q0.z+q1.z+q2.z+q3.z, q0.w+q1.w+q2.w+q3.w);
    }

    float4 a0 = y0[tid], a1 = y1[tid], a2 = y2[tid], a3 = y3[tid];
    float4 xv = xc[tid];
    float4 v = make_float4(a0.x+a1.x+a2.x+a3.x + sd.x*xv.x,
                           a0.y+a1.y+a2.y+a3.y + sd.y*xv.y,
                           a0.z+a1.z+a2.z+a3.z + sd.z*xv.z,
                           a0.w+a1.w+a2.w+a3.w + sd.w*xv.w);
    float s  = v.x+v.y+v.z+v.w;
    float sq = v.x*v.x + v.y*v.y + v.z*v.z + v.w*v.w;
    #pragma unroll
    for (int o=16;o>0;o>>=1){
        s  += __shfl_xor_sync(0xffffffffu, s,  o);
        sq += __shfl_xor_sync(0xffffffffu, sq, o);
    }
    __shared__ float ss[4], sqq[4];
    const int wid = tid >> 5, lane = tid & 31;
    if (lane==0){ ss[wid]=s; sqq[wid]=sq; }
    __syncthreads();
    s  = ss[0]+ss[1]+ss[2]+ss[3];
    sq = sqq[0]+sqq[1]+sqq[2]+sqq[3];
    const float mu  = s * (1.f/512.f);
    const float var = sq * (1.f/512.f) - mu*mu;
    const float rs  = rsqrtf(var + 1e-5f);

    float4 g4 = ((const float4*)ln_g)[tid];
    float4 b4 = ((const float4*)ln_b)[tid];
    float4 z4 = ((const float4*)z)[tid];
    v.x = ((v.x-mu)*rs*g4.x + b4.x) * z4.x;
    v.y = ((v.y-mu)*rs*g4.y + b4.y) * z4.y;
    v.z = ((v.z-mu)*rs*g4.z + b4.z) * z4.z;
    v.w = ((v.w-mu)*rs*g4.w + b4.w) * z4.w;
    ((float4*)(g_ysum + (size_t)row*DI))[tid] = v;
}

// ---------------- launch ----------------
extern "C" void kernel_launch(void* const* d_in, const int* in_sizes, int n_in,
                              void* d_out, int out_size){
    const float* x          = (const float*)d_in[0];
    const float* in_proj_w  = (const float*)d_in[1];
    const float* conv_w     = (const float*)d_in[2];
    const float* conv_b     = (const float*)d_in[3];
    const float* x_proj_w   = (const float*)d_in[4];
    const float* dt_proj_w  = (const float*)d_in[5];
    const float* dt_bias    = (const float*)d_in[6];
    const float* A_logs     = (const float*)d_in[7];
    const float* Ds         = (const float*)d_in[8];
    const float* ln_g       = (const float*)d_in[9];
    const float* ln_b       = (const float*)d_in[10];
    const float* out_proj_w = (const float*)d_in[11];
    float* out = (float*)d_out;

    chain_flag_kernel   <<<1, 256>>>(A_logs);
    gemm_tc<256,0,128>  <<<dim3(64,16), 256>>>(x, in_proj_w, nullptr);
    conv_silu           <<<dim3(32, 8), 512>>>(conv_w, conv_b);
    gemm_tc<512,2, 64>  <<<dim3(128,3), 128>>>(nullptr, x_proj_w, nullptr);
    scan_part1_chain    <<<dim3(4, NCH, 32), 128>>>(dt_proj_w, dt_bias, A_logs);
    scan_part1_gen      <<<592, 128>>>(dt_proj_w, dt_bias, A_logs);
    scan_combine        <<<1024, 256>>>(A_logs);
    scan_part3_chain    <<<dim3(4, NCH, 32), 128>>>();
    scan_part3_gen      <<<592, 128>>>(dt_proj_w, dt_bias, A_logs);
    norm_kernel         <<<8192, 128>>>(ln_g, ln_b, Ds);
    gemm_tc<512,1,128>  <<<dim3(64, 4), 256>>>(nullptr, out_proj_w, out);
}